// round 11
// baseline (speedup 1.0000x reference)
#include <cuda_runtime.h>
#include <math.h>

// Problem constants
#define NB    256   // batch
#define ND    256   // dim
#define HQ    12
#define WQ    26
#define NSP   312   // H*W query positions
#define NJ    18    // 3*6 kv positions
#define NHEAD 16
#define DHEAD 16
#define TI    16    // i-tile size
#define NTIL  20    // ceil(312/16)
#define KROW  20    // padded row stride for k/v/kv smem (80B, 16B-aligned rows)
#define BROW  292   // bias buffer il-stride
#define NTHR  288   // 16*18 = one MLP point per thread

typedef unsigned long long ull;

// Packed fp32x2 helpers (sm_100+): exact fp32 math, 2 MACs per issue slot.
__device__ __forceinline__ ull pk2(float lo, float hi) {
    ull d;
    asm("mov.b64 %0, {%1, %2};" : "=l"(d) : "r"(__float_as_uint(lo)), "r"(__float_as_uint(hi)));
    return d;
}
__device__ __forceinline__ void upk2(float& lo, float& hi, ull v) {
    unsigned a, b;
    asm("mov.b64 {%0, %1}, %2;" : "=r"(a), "=r"(b) : "l"(v));
    lo = __uint_as_float(a); hi = __uint_as_float(b);
}
__device__ __forceinline__ ull fma2(ull a, ull b, ull c) {
    ull d;
    asm("fma.rn.f32x2 %0, %1, %2, %3;" : "=l"(d) : "l"(a), "l"(b), "l"(c));
    return d;
}

struct __align__(16) SM {
    float qsh[256];        // q row
    float ksh[256 * KROW]; // k, [c][j]
    float vsh[256 * KROW]; // v, [c][j]
    float buf[5120];       // phase2: kv[c][KROW]; phase3: bias/attn [il][h][j] stride BROW
    float w1[128];         // cpb_w1 [k][2]
    float b1[64];
    float w2q[4096];       // cpb_w2 pair-interleaved: [k][m2] -> {w2[2*m2][k], w2[2*m2+1][k]}
    float b2[64];
    float w3t[1024];       // cpb_w3 transposed: [m][t]
    float b3[16];
    float cw[312];         // conv1d_w
    float gk0[20], gk1[20], sxs[20], sys[20];
    float Ash[288];        // A[h][j]
    float pp[256];         // pooled_pre
    float red[288];        // reductions
    float stats[4];
};

__global__ void __launch_bounds__(NTHR)
sca_kernel(const float* __restrict__ x, const float* __restrict__ q,
           const float* __restrict__ w_off_dw, const float* __restrict__ b_off_dw,
           const float* __restrict__ w_off_pw,
           const float* __restrict__ wk, const float* __restrict__ wv,
           const float* __restrict__ w_out, const float* __restrict__ b_out,
           const float* __restrict__ cpb_w1, const float* __restrict__ cpb_b1,
           const float* __restrict__ cpb_w2, const float* __restrict__ cpb_b2,
           const float* __restrict__ cpb_w3, const float* __restrict__ cpb_b3,
           const float* __restrict__ conv1d_w, const float* __restrict__ conv1d_b,
           const float* __restrict__ ln_g, const float* __restrict__ ln_b,
           float* __restrict__ out)
{
    extern __shared__ char smem_raw[];
    SM* sm = reinterpret_cast<SM*>(smem_raw);
    const int tid  = threadIdx.x;
    const int b    = blockIdx.x;
    const int lane = tid & 31;
    const int wid  = tid >> 5;

    // ---- load q + CPB weights + conv1d_w into smem ----
    if (tid < 256) sm->qsh[tid] = q[b * ND + tid];
    for (int idx = tid; idx < 4096; idx += NTHR) {
        int m = idx >> 6, k = idx & 63;
        sm->w2q[(k * 32 + (m >> 1)) * 2 + (m & 1)] = cpb_w2[idx];
    }
    for (int idx = tid; idx < 1024; idx += NTHR) {
        int t = idx >> 6, m = idx & 63;
        sm->w3t[m * 16 + t] = cpb_w3[idx];
    }
    if (tid < 128) sm->w1[tid] = cpb_w1[tid];
    if (tid < 64) { sm->b1[tid] = cpb_b1[tid]; sm->b2[tid] = cpb_b2[tid]; }
    if (tid < 16) sm->b3[tid] = cpb_b3[tid];
    for (int idx = tid; idx < NSP; idx += NTHR) sm->cw[idx] = conv1d_w[idx];
    __syncthreads();

    // ================= Phase 1: offsets =================
    if (tid < 256) {
        const int c = tid;
        float wdw[36];
        #pragma unroll
        for (int t = 0; t < 36; t++) wdw[t] = __ldg(w_off_dw + c * 36 + t);
        const float bdw = __ldg(b_off_dw + c);
        const float pw0 = __ldg(w_off_pw + c);
        const float pw1 = __ldg(w_off_pw + 256 + c);
        const int cbase = (c * 56) & 255;

        float p0[18], p1[18];
        #pragma unroll
        for (int oh = 0; oh < 3; oh++) {
            #pragma unroll
            for (int ow = 0; ow < 6; ow++) {
                float acc = bdw;
                #pragma unroll
                for (int kh = 0; kh < 6; kh++) {
                    int ih = oh * 4 - 1 + kh;
                    if (ih < 0 || ih >= HQ) continue;
                    #pragma unroll
                    for (int kw = 0; kw < 6; kw++) {
                        int iw = ow * 4 - 1 + kw;
                        if (iw < 0 || iw >= WQ) continue;
                        int s = ih * WQ + iw;
                        acc = fmaf(wdw[kh * 6 + kw], sm->qsh[(cbase + s) & 255], acc);
                    }
                }
                float g = 0.5f * acc * (1.0f + erff(acc * 0.70710678118654752f));
                p0[oh * 6 + ow] = pw0 * g;
                p1[oh * 6 + ow] = pw1 * g;
            }
        }
        #pragma unroll
        for (int t = 0; t < 18; t++) {
            #pragma unroll
            for (int o = 16; o > 0; o >>= 1) {
                p0[t] += __shfl_xor_sync(0xffffffffu, p0[t], o);
                p1[t] += __shfl_xor_sync(0xffffffffu, p1[t], o);
            }
        }
        if (lane == 0) {
            #pragma unroll
            for (int t = 0; t < 18; t++) {
                sm->red[wid * 36 + t]      = p0[t];
                sm->red[wid * 36 + 18 + t] = p1[t];
            }
        }
    }
    __syncthreads();
    if (tid < 36) {
        float a = 0.f;
        #pragma unroll
        for (int w8 = 0; w8 < 8; w8++) a += sm->red[w8 * 36 + tid];
        float off = tanhf(a) * 4.0f;
        if (tid < 18) {            // channel 0 -> x (grid col index)
            int j = tid;
            float vg0 = (float)(j % 6) + off;
            float n0  = 2.0f * vg0 / 2.0f - 1.0f;
            sm->gk0[j] = n0;
            sm->sxs[j] = ((n0 + 1.0f) * 26.0f - 1.0f) * 0.5f;
        } else {                   // channel 1 -> y (grid row index)
            int j = tid - 18;
            float vg1 = (float)(j / 6) + off;
            float n1  = 2.0f * vg1 / 5.0f - 1.0f;
            sm->gk1[j] = n1;
            sm->sys[j] = ((n1 + 1.0f) * 12.0f - 1.0f) * 0.5f;
        }
    }
    __syncthreads();

    // ================= Phase 2: grid-sample + k/v =================
    if (tid < 256) {
        const int c = tid;
        float* kvsh = sm->buf;                 // [c][KROW]
        const float* xrow = x + ((size_t)b * ND + c) * NSP;
        #pragma unroll
        for (int j = 0; j < NJ; j++) {
            float xs = sm->sxs[j], ys = sm->sys[j];
            float x0f = floorf(xs), y0f = floorf(ys);
            int x0 = (int)x0f, y0 = (int)y0f;
            float wx1 = xs - x0f, wx0 = 1.0f - wx1;
            float wy1 = ys - y0f, wy0 = 1.0f - wy1;
            int x1 = x0 + 1, y1 = y0 + 1;
            bool vx0 = (x0 >= 0) & (x0 < WQ), vx1 = (x1 >= 0) & (x1 < WQ);
            bool vy0 = (y0 >= 0) & (y0 < HQ), vy1 = (y1 >= 0) & (y1 < HQ);
            float v00 = (vx0 & vy0) ? __ldg(xrow + y0 * WQ + x0) : 0.f;
            float v01 = (vx1 & vy0) ? __ldg(xrow + y0 * WQ + x1) : 0.f;
            float v10 = (vx0 & vy1) ? __ldg(xrow + y1 * WQ + x0) : 0.f;
            float v11 = (vx1 & vy1) ? __ldg(xrow + y1 * WQ + x1) : 0.f;
            kvsh[c * KROW + j] = (v00 * wx0 + v01 * wx1) * wy0 + (v10 * wx0 + v11 * wx1) * wy1;
        }
    }
    __syncthreads();
    if (tid < 256) {   // k/v GEMM (packed f32x2): thread = output channel
        const int o = tid;
        ull ak2[9], av2[9];
        #pragma unroll
        for (int j2 = 0; j2 < 9; j2++) { ak2[j2] = 0ULL; av2[j2] = 0ULL; }
        const float* wkr = wk + o * ND;
        const float* wvr = wv + o * ND;
        for (int c4 = 0; c4 < ND; c4 += 4) {
            float4 a = *(const float4*)(wkr + c4);
            float4 v = *(const float4*)(wvr + c4);
            const float wkx[4] = {a.x, a.y, a.z, a.w};
            const float wvx[4] = {v.x, v.y, v.z, v.w};
            #pragma unroll
            for (int u = 0; u < 4; u++) {
                const float* kvr = sm->buf + (c4 + u) * KROW;
                const ulonglong2* kp = (const ulonglong2*)kvr;
                ulonglong2 pa = kp[0], pb = kp[1], pc = kp[2], pd = kp[3];
                ull pe = *(const ull*)(kvr + 16);
                ull wkk = pk2(wkx[u], wkx[u]);
                ull wvv = pk2(wvx[u], wvx[u]);
                ak2[0] = fma2(wkk, pa.x, ak2[0]); av2[0] = fma2(wvv, pa.x, av2[0]);
                ak2[1] = fma2(wkk, pa.y, ak2[1]); av2[1] = fma2(wvv, pa.y, av2[1]);
                ak2[2] = fma2(wkk, pb.x, ak2[2]); av2[2] = fma2(wvv, pb.x, av2[2]);
                ak2[3] = fma2(wkk, pb.y, ak2[3]); av2[3] = fma2(wvv, pb.y, av2[3]);
                ak2[4] = fma2(wkk, pc.x, ak2[4]); av2[4] = fma2(wvv, pc.x, av2[4]);
                ak2[5] = fma2(wkk, pc.y, ak2[5]); av2[5] = fma2(wvv, pc.y, av2[5]);
                ak2[6] = fma2(wkk, pd.x, ak2[6]); av2[6] = fma2(wvv, pd.x, av2[6]);
                ak2[7] = fma2(wkk, pd.y, ak2[7]); av2[7] = fma2(wvv, pd.y, av2[7]);
                ak2[8] = fma2(wkk, pe,   ak2[8]); av2[8] = fma2(wvv, pe,   av2[8]);
            }
        }
        float* krow = sm->ksh + o * KROW;
        float* vrow = sm->vsh + o * KROW;
        #pragma unroll
        for (int j2 = 0; j2 < 9; j2++) {
            *(ull*)(krow + 2 * j2) = ak2[j2];
            *(ull*)(vrow + 2 * j2) = av2[j2];
        }
    }
    __syncthreads();

    // ================= Phase 3: CPB MLP + attention, tiled over i =================
    float A_reg = 0.f;                 // one (h,j) pair per thread: 288 = 16*18 exactly
    const int hA = tid / 18, jA = tid % 18;
    const int ilM = tid / 18, jM = tid % 18;   // MLP point: one per thread

    for (int tile = 0; tile < NTIL; tile++) {
        const int i0 = tile * TI;
        // ---- (a) CPB MLP (packed f32x2): one point per thread ----
        {
            const int i = i0 + ilM;
            if (i < NSP) {
                int wq_i = i % WQ, hq_i = i / WQ;
                float gq0 = 2.0f * (float)wq_i / 11.0f - 1.0f;
                float gq1 = 2.0f * (float)hq_i / 25.0f - 1.0f;
                float px = gq0 - sm->gk0[jM];
                float py = gq1 - sm->gk1[jM];
                float u0 = copysignf(log1pf(fabsf(px)), px);
                float u1 = copysignf(log1pf(fabsf(py)), py);
                float h1v[64];
                #pragma unroll
                for (int k = 0; k < 64; k++) {
                    float2 w = ((const float2*)sm->w1)[k];
                    h1v[k] = fmaxf(fmaf(w.x, u0, fmaf(w.y, u1, sm->b1[k])), 0.f);
                }
                ull op[8];
                #pragma unroll
                for (int t = 0; t < 8; t++) op[t] = *(const ull*)(sm->b3 + 2 * t);
                #pragma unroll 1
                for (int mb = 0; mb < 2; mb++) {
                    // accumulators: 16 m-pairs = 32 channels of layer-2 output
                    ull acc[16];
                    #pragma unroll
                    for (int p = 0; p < 16; p++)
                        acc[p] = *(const ull*)(sm->b2 + (mb * 16 + p) * 2);
                    #pragma unroll 4
                    for (int k = 0; k < 64; k++) {
                        ull hh = pk2(h1v[k], h1v[k]);
                        const ulonglong2* w4 = (const ulonglong2*)(sm->w2q + (k * 32 + mb * 16) * 2);
                        #pragma unroll
                        for (int pq = 0; pq < 8; pq++) {
                            ulonglong2 wp = w4[pq];
                            acc[2 * pq]     = fma2(wp.x, hh, acc[2 * pq]);
                            acc[2 * pq + 1] = fma2(wp.y, hh, acc[2 * pq + 1]);
                        }
                    }
                    // relu + layer-3 (packed over t-pairs)
                    #pragma unroll
                    for (int p = 0; p < 16; p++) {
                        float e0, e1; upk2(e0, e1, acc[p]);
                        e0 = fmaxf(e0, 0.f); e1 = fmaxf(e1, 0.f);
                        int m0 = (mb * 16 + p) * 2;
                        ull hh0 = pk2(e0, e0);
                        const ulonglong2* wr0 = (const ulonglong2*)(sm->w3t + m0 * 16);
                        ulonglong2 a0 = wr0[0], a1 = wr0[1], a2 = wr0[2], a3 = wr0[3];
                        op[0] = fma2(a0.x, hh0, op[0]); op[1] = fma2(a0.y, hh0, op[1]);
                        op[2] = fma2(a1.x, hh0, op[2]); op[3] = fma2(a1.y, hh0, op[3]);
                        op[4] = fma2(a2.x, hh0, op[4]); op[5] = fma2(a2.y, hh0, op[5]);
                        op[6] = fma2(a3.x, hh0, op[6]); op[7] = fma2(a3.y, hh0, op[7]);
                        ull hh1 = pk2(e1, e1);
                        const ulonglong2* wr1 = (const ulonglong2*)(sm->w3t + (m0 + 1) * 16);
                        ulonglong2 c0 = wr1[0], c1 = wr1[1], c2 = wr1[2], c3 = wr1[3];
                        op[0] = fma2(c0.x, hh1, op[0]); op[1] = fma2(c0.y, hh1, op[1]);
                        op[2] = fma2(c1.x, hh1, op[2]); op[3] = fma2(c1.y, hh1, op[3]);
                        op[4] = fma2(c2.x, hh1, op[4]); op[5] = fma2(c2.y, hh1, op[5]);
                        op[6] = fma2(c3.x, hh1, op[6]); op[7] = fma2(c3.y, hh1, op[7]);
                    }
                }
                // bias layout: [il][h][j], il-stride BROW, h-stride 18
                float* dst = sm->buf + ilM * BROW + jM;
                #pragma unroll
                for (int t = 0; t < 8; t++) {
                    float lo, hi; upk2(lo, hi, op[t]);
                    dst[(2 * t) * 18]     = lo;
                    dst[(2 * t + 1) * 18] = hi;
                }
            }
        }
        __syncthreads();
        // ---- (c) qk (packed) + bias + softmax + conv1d weighting ----
        if (tid < 256) {
            const int h = tid >> 4, il = tid & 15;
            const int i = i0 + il;
            float* brow = sm->buf + il * BROW + h * 18;
            if (i < NSP) {
                ull s2[9];
                #pragma unroll
                for (int j2 = 0; j2 < 9; j2++) s2[j2] = *(const ull*)(brow + 2 * j2);
                #pragma unroll
                for (int d = 0; d < DHEAD; d++) {
                    int c = h * 16 + d;
                    float qv = 0.25f * sm->qsh[(c * 56 + i) & 255];
                    ull qq = pk2(qv, qv);
                    const float* krow = sm->ksh + c * KROW;
                    const ulonglong2* kr = (const ulonglong2*)krow;
                    ulonglong2 ka = kr[0], kb = kr[1], kc = kr[2], kd = kr[3];
                    ull ke = *(const ull*)(krow + 16);
                    s2[0] = fma2(qq, ka.x, s2[0]); s2[1] = fma2(qq, ka.y, s2[1]);
                    s2[2] = fma2(qq, kb.x, s2[2]); s2[3] = fma2(qq, kb.y, s2[3]);
                    s2[4] = fma2(qq, kc.x, s2[4]); s2[5] = fma2(qq, kc.y, s2[5]);
                    s2[6] = fma2(qq, kd.x, s2[6]); s2[7] = fma2(qq, kd.y, s2[7]);
                    s2[8] = fma2(qq, ke,   s2[8]);
                }
                float srow[18];
                #pragma unroll
                for (int j2 = 0; j2 < 9; j2++) upk2(srow[2 * j2], srow[2 * j2 + 1], s2[j2]);
                float mx = srow[0];
                #pragma unroll
                for (int j = 1; j < NJ; j++) mx = fmaxf(mx, srow[j]);
                float ssum = 0.f;
                #pragma unroll
                for (int j = 0; j < NJ; j++) { float e = __expf(srow[j] - mx); srow[j] = e; ssum += e; }
                float sc = sm->cw[i] / ssum;
                #pragma unroll
                for (int j = 0; j < NJ; j++) brow[j] = srow[j] * sc;
            } else {
                #pragma unroll
                for (int j = 0; j < NJ; j++) brow[j] = 0.f;
            }
        }
        __syncthreads();
        // ---- (e) reduce over il into A: one (h,j) pair per thread ----
        {
            const float* src = sm->buf + hA * 18 + jA;
            float a = 0.f;
            #pragma unroll
            for (int il = 0; il < TI; il++) a += src[il * BROW];
            A_reg += a;
        }
        __syncthreads();
    }
    sm->Ash[hA * NJ + jA] = A_reg;
    __syncthreads();

    // ================= Tail: pooled attention output -> w_out -> residual -> LN =================
    if (tid < 256) {
        const int h = tid >> 4;
        const float* vr = sm->vsh + tid * KROW;
        const float* Ar = sm->Ash + h * NJ;
        const ulonglong2* vr2 = (const ulonglong2*)vr;
        ulonglong2 va = vr2[0], vb = vr2[1], vc = vr2[2], vd = vr2[3];
        ull ve = *(const ull*)(vr + 16);
        ull acc2 = 0ULL;
        acc2 = fma2(*(const ull*)(Ar + 0),  va.x, acc2);
        acc2 = fma2(*(const ull*)(Ar + 2),  va.y, acc2);
        acc2 = fma2(*(const ull*)(Ar + 4),  vb.x, acc2);
        acc2 = fma2(*(const ull*)(Ar + 6),  vb.y, acc2);
        acc2 = fma2(*(const ull*)(Ar + 8),  vc.x, acc2);
        acc2 = fma2(*(const ull*)(Ar + 10), vc.y, acc2);
        acc2 = fma2(*(const ull*)(Ar + 12), vd.x, acc2);
        acc2 = fma2(*(const ull*)(Ar + 14), vd.y, acc2);
        acc2 = fma2(*(const ull*)(Ar + 16), ve,   acc2);
        float lo, hi; upk2(lo, hi, acc2);
        sm->pp[tid] = lo + hi;
    }
    __syncthreads();
    {
        float y = 0.f;
        if (tid < 256) {
            float s0 = 0.f, s1 = 0.f, s2v = 0.f, s3v = 0.f;
            for (int t = 0; t < NSP; t += 4) {
                s0 += sm->cw[t]; s1 += sm->cw[t + 1]; s2v += sm->cw[t + 2]; s3v += sm->cw[t + 3];
            }
            float sumcw = (s0 + s1) + (s2v + s3v);
            float accb = sumcw * __ldg(b_out + tid) + __ldg(conv1d_b);
            const ulonglong2* wor2 = (const ulonglong2*)(w_out + tid * ND);
            const ulonglong2* pp2  = (const ulonglong2*)sm->pp;
            ull acc2 = 0ULL;
            for (int t = 0; t < 64; t++) {
                ulonglong2 wq4 = wor2[t];
                ulonglong2 pq4 = pp2[t];
                acc2 = fma2(wq4.x, pq4.x, acc2);
                acc2 = fma2(wq4.y, pq4.y, acc2);
            }
            float lo, hi; upk2(lo, hi, acc2);
            y = accb + (lo + hi) + sm->qsh[tid];
            float s = y, sq = y * y;
            #pragma unroll
            for (int o = 16; o > 0; o >>= 1) {
                s  += __shfl_xor_sync(0xffffffffu, s,  o);
                sq += __shfl_xor_sync(0xffffffffu, sq, o);
            }
            if (lane == 0) { sm->red[wid] = s; sm->red[8 + wid] = sq; }
        }
        __syncthreads();
        if (tid == 0) {
            float t1 = 0.f, t2 = 0.f;
            #pragma unroll
            for (int w8 = 0; w8 < 8; w8++) { t1 += sm->red[w8]; t2 += sm->red[8 + w8]; }
            float mu = t1 * (1.0f / 256.0f);
            sm->stats[0] = mu;
            sm->stats[1] = t2 * (1.0f / 256.0f) - mu * mu;
        }
        __syncthreads();
        if (tid < 256) {
            float mu = sm->stats[0], var = sm->stats[1];
            out[b * ND + tid] = (y - mu) * rsqrtf(var + 1e-5f) * __ldg(ln_g + tid) + __ldg(ln_b + tid);
        }
    }
}

extern "C" void kernel_launch(void* const* d_in, const int* in_sizes, int n_in,
                              void* d_out, int out_size)
{
    const float* x        = (const float*)d_in[0];
    const float* q        = (const float*)d_in[1];
    const float* w_off_dw = (const float*)d_in[2];
    const float* b_off_dw = (const float*)d_in[3];
    const float* w_off_pw = (const float*)d_in[4];
    const float* wk       = (const float*)d_in[5];
    const float* wv       = (const float*)d_in[6];
    const float* w_out    = (const float*)d_in[7];
    const float* b_out    = (const float*)d_in[8];
    const float* cpb_w1   = (const float*)d_in[9];
    const float* cpb_b1   = (const float*)d_in[10];
    const float* cpb_w2   = (const float*)d_in[11];
    const float* cpb_b2   = (const float*)d_in[12];
    const float* cpb_w3   = (const float*)d_in[13];
    const float* cpb_b3   = (const float*)d_in[14];
    const float* conv1d_w = (const float*)d_in[15];
    const float* conv1d_b = (const float*)d_in[16];
    const float* ln_g     = (const float*)d_in[17];
    const float* ln_b     = (const float*)d_in[18];
    float* out = (float*)d_out;

    (void)in_sizes; (void)n_in; (void)out_size;

    cudaFuncSetAttribute(sca_kernel, cudaFuncAttributeMaxDynamicSharedMemorySize, (int)sizeof(SM));
    sca_kernel<<<NB, NTHR, sizeof(SM)>>>(x, q, w_off_dw, b_off_dw, w_off_pw, wk, wv,
                                         w_out, b_out, cpb_w1, cpb_b1, cpb_w2, cpb_b2,
                                         cpb_w3, cpb_b3, conv1d_w, conv1d_b, ln_g, ln_b, out);
}

// round 12
// speedup vs baseline: 1.1555x; 1.1555x over previous
#include <cuda_runtime.h>
#include <math.h>

// Problem constants
#define NB    256   // batch
#define ND    256   // dim
#define HQ    12
#define WQ    26
#define NSP   312   // H*W query positions
#define NJ    18    // 3*6 kv positions
#define NHEAD 16
#define DHEAD 16
#define TI    16    // i-tile size
#define NTIL  20    // ceil(312/16)
#define KROW  20    // padded row stride for k/v/kv smem (80B, 16B-aligned rows)
#define BROW  292   // bias buffer il-stride
#define NTHR  288   // 16*18 = one MLP point per thread

struct __align__(16) SM {
    float qsh[256];        // q row
    float ksh[256 * KROW]; // k, [c][j]
    float vsh[256 * KROW]; // v, [c][j]
    float buf[5120];       // phase2: kv[c][KROW]; phase3: bias/attn [il][h][j] stride BROW
    float w1[128];         // cpb_w1 [k][2]
    float b1[64];
    float w2t[4096];       // cpb_w2 TRANSPOSED: [k][m]
    float b2[64];
    float w3t[1024];       // cpb_w3 transposed: [m][t]
    float b3[16];
    float cw[312];         // conv1d_w
    float gk0[20], gk1[20], sxs[20], sys[20];
    float Ash[288];        // A[h][j]
    float pp[256];         // pooled_pre
    float red[288];        // reductions
    float stats[4];
};

__global__ void __launch_bounds__(NTHR, 2)
sca_kernel(const float* __restrict__ x, const float* __restrict__ q,
           const float* __restrict__ w_off_dw, const float* __restrict__ b_off_dw,
           const float* __restrict__ w_off_pw,
           const float* __restrict__ wk, const float* __restrict__ wv,
           const float* __restrict__ w_out, const float* __restrict__ b_out,
           const float* __restrict__ cpb_w1, const float* __restrict__ cpb_b1,
           const float* __restrict__ cpb_w2, const float* __restrict__ cpb_b2,
           const float* __restrict__ cpb_w3, const float* __restrict__ cpb_b3,
           const float* __restrict__ conv1d_w, const float* __restrict__ conv1d_b,
           const float* __restrict__ ln_g, const float* __restrict__ ln_b,
           float* __restrict__ out)
{
    extern __shared__ char smem_raw[];
    SM* sm = reinterpret_cast<SM*>(smem_raw);
    const int tid  = threadIdx.x;
    const int b    = blockIdx.x;
    const int lane = tid & 31;
    const int wid  = tid >> 5;

    // ---- load q + CPB weights + conv1d_w into smem ----
    if (tid < 256) sm->qsh[tid] = q[b * ND + tid];
    for (int idx = tid; idx < 4096; idx += NTHR) {
        int m = idx >> 6, k = idx & 63;
        sm->w2t[k * 64 + m] = cpb_w2[idx];        // transpose to [k][m]
    }
    for (int idx = tid; idx < 1024; idx += NTHR) {
        int t = idx >> 6, m = idx & 63;
        sm->w3t[m * 16 + t] = cpb_w3[idx];
    }
    if (tid < 128) sm->w1[tid] = cpb_w1[tid];
    if (tid < 64) { sm->b1[tid] = cpb_b1[tid]; sm->b2[tid] = cpb_b2[tid]; }
    if (tid < 16) sm->b3[tid] = cpb_b3[tid];
    for (int idx = tid; idx < NSP; idx += NTHR) sm->cw[idx] = conv1d_w[idx];
    __syncthreads();

    // ================= Phase 1: offsets =================
    if (tid < 256) {
        const int c = tid;
        float wdw[36];
        #pragma unroll
        for (int t = 0; t < 36; t++) wdw[t] = __ldg(w_off_dw + c * 36 + t);
        const float bdw = __ldg(b_off_dw + c);
        const float pw0 = __ldg(w_off_pw + c);
        const float pw1 = __ldg(w_off_pw + 256 + c);
        const int cbase = (c * 56) & 255;

        float p0[18], p1[18];
        #pragma unroll
        for (int oh = 0; oh < 3; oh++) {
            #pragma unroll
            for (int ow = 0; ow < 6; ow++) {
                float acc = bdw;
                #pragma unroll
                for (int kh = 0; kh < 6; kh++) {
                    int ih = oh * 4 - 1 + kh;
                    if (ih < 0 || ih >= HQ) continue;
                    #pragma unroll
                    for (int kw = 0; kw < 6; kw++) {
                        int iw = ow * 4 - 1 + kw;
                        if (iw < 0 || iw >= WQ) continue;
                        int s = ih * WQ + iw;
                        acc = fmaf(wdw[kh * 6 + kw], sm->qsh[(cbase + s) & 255], acc);
                    }
                }
                float g = 0.5f * acc * (1.0f + erff(acc * 0.70710678118654752f));
                p0[oh * 6 + ow] = pw0 * g;
                p1[oh * 6 + ow] = pw1 * g;
            }
        }
        #pragma unroll
        for (int t = 0; t < 18; t++) {
            #pragma unroll
            for (int o = 16; o > 0; o >>= 1) {
                p0[t] += __shfl_xor_sync(0xffffffffu, p0[t], o);
                p1[t] += __shfl_xor_sync(0xffffffffu, p1[t], o);
            }
        }
        if (lane == 0) {
            #pragma unroll
            for (int t = 0; t < 18; t++) {
                sm->red[wid * 36 + t]      = p0[t];
                sm->red[wid * 36 + 18 + t] = p1[t];
            }
        }
    }
    __syncthreads();
    if (tid < 36) {
        float a = 0.f;
        #pragma unroll
        for (int w8 = 0; w8 < 8; w8++) a += sm->red[w8 * 36 + tid];
        float off = tanhf(a) * 4.0f;
        if (tid < 18) {            // channel 0 -> x (grid col index)
            int j = tid;
            float vg0 = (float)(j % 6) + off;
            float n0  = 2.0f * vg0 / 2.0f - 1.0f;
            sm->gk0[j] = n0;
            sm->sxs[j] = ((n0 + 1.0f) * 26.0f - 1.0f) * 0.5f;
        } else {                   // channel 1 -> y (grid row index)
            int j = tid - 18;
            float vg1 = (float)(j / 6) + off;
            float n1  = 2.0f * vg1 / 5.0f - 1.0f;
            sm->gk1[j] = n1;
            sm->sys[j] = ((n1 + 1.0f) * 12.0f - 1.0f) * 0.5f;
        }
    }
    __syncthreads();

    // ================= Phase 2: grid-sample + k/v =================
    if (tid < 256) {
        const int c = tid;
        float* kvsh = sm->buf;                 // [c][KROW]
        const float* xrow = x + ((size_t)b * ND + c) * NSP;
        #pragma unroll
        for (int j = 0; j < NJ; j++) {
            float xs = sm->sxs[j], ys = sm->sys[j];
            float x0f = floorf(xs), y0f = floorf(ys);
            int x0 = (int)x0f, y0 = (int)y0f;
            float wx1 = xs - x0f, wx0 = 1.0f - wx1;
            float wy1 = ys - y0f, wy0 = 1.0f - wy1;
            int x1 = x0 + 1, y1 = y0 + 1;
            bool vx0 = (x0 >= 0) & (x0 < WQ), vx1 = (x1 >= 0) & (x1 < WQ);
            bool vy0 = (y0 >= 0) & (y0 < HQ), vy1 = (y1 >= 0) & (y1 < HQ);
            float v00 = (vx0 & vy0) ? __ldg(xrow + y0 * WQ + x0) : 0.f;
            float v01 = (vx1 & vy0) ? __ldg(xrow + y0 * WQ + x1) : 0.f;
            float v10 = (vx0 & vy1) ? __ldg(xrow + y1 * WQ + x0) : 0.f;
            float v11 = (vx1 & vy1) ? __ldg(xrow + y1 * WQ + x1) : 0.f;
            kvsh[c * KROW + j] = (v00 * wx0 + v01 * wx1) * wy0 + (v10 * wx0 + v11 * wx1) * wy1;
        }
    }
    __syncthreads();
    if (tid < 256) {   // k/v GEMM: thread = output channel
        const int o = tid;
        float ak[18], av[18];
        #pragma unroll
        for (int j = 0; j < NJ; j++) { ak[j] = 0.f; av[j] = 0.f; }
        const float* wkr = wk + o * ND;
        const float* wvr = wv + o * ND;
        const float* kvsh = sm->buf;
        for (int c4 = 0; c4 < ND; c4 += 4) {
            float4 a = *(const float4*)(wkr + c4);
            float4 v = *(const float4*)(wvr + c4);
            const float wkx[4] = {a.x, a.y, a.z, a.w};
            const float wvx[4] = {v.x, v.y, v.z, v.w};
            #pragma unroll
            for (int u = 0; u < 4; u++) {
                const float* kvr = kvsh + (c4 + u) * KROW;
                float wk1 = wkx[u], wv1 = wvx[u];
                #pragma unroll
                for (int j = 0; j < NJ; j++) {
                    float kvv = kvr[j];
                    ak[j] = fmaf(wk1, kvv, ak[j]);
                    av[j] = fmaf(wv1, kvv, av[j]);
                }
            }
        }
        #pragma unroll
        for (int j = 0; j < NJ; j++) {
            sm->ksh[o * KROW + j] = ak[j];
            sm->vsh[o * KROW + j] = av[j];
        }
    }
    __syncthreads();

    // ================= Phase 3: CPB MLP + attention, tiled over i =================
    float A_reg = 0.f;                 // one (h,j) pair per thread: 288 = 16*18 exactly
    const int hA = tid / 18, jA = tid % 18;
    const int ilM = tid / 18, jM = tid % 18;   // MLP point: one per thread

    for (int tile = 0; tile < NTIL; tile++) {
        const int i0 = tile * TI;
        // ---- (a) CPB MLP: one point per thread; layer-1 recomputed per m-block
        //      to keep register pressure low (2 CTAs/SM). ----
        {
            const int i = i0 + ilM;
            if (i < NSP) {
                int wq_i = i % WQ, hq_i = i / WQ;
                float gq0 = 2.0f * (float)wq_i / 11.0f - 1.0f;
                float gq1 = 2.0f * (float)hq_i / 25.0f - 1.0f;
                float px = gq0 - sm->gk0[jM];
                float py = gq1 - sm->gk1[jM];
                float u0 = copysignf(log1pf(fabsf(px)), px);
                float u1 = copysignf(log1pf(fabsf(py)), py);
                float o16[16];
                #pragma unroll
                for (int t = 0; t < 16; t++) o16[t] = sm->b3[t];
                #pragma unroll 1
                for (int mb = 0; mb < 64; mb += 32) {
                    float acc[32];
                    #pragma unroll
                    for (int m = 0; m < 32; m++) acc[m] = sm->b2[mb + m];
                    #pragma unroll 4
                    for (int k = 0; k < 64; k++) {
                        float2 w = ((const float2*)sm->w1)[k];
                        float h1 = fmaxf(fmaf(w.x, u0, fmaf(w.y, u1, sm->b1[k])), 0.f);
                        const float* w2r = sm->w2t + k * 64 + mb;
                        #pragma unroll
                        for (int m4 = 0; m4 < 32; m4 += 4) {
                            float4 ww = *(const float4*)(w2r + m4);
                            acc[m4]     = fmaf(ww.x, h1, acc[m4]);
                            acc[m4 + 1] = fmaf(ww.y, h1, acc[m4 + 1]);
                            acc[m4 + 2] = fmaf(ww.z, h1, acc[m4 + 2]);
                            acc[m4 + 3] = fmaf(ww.w, h1, acc[m4 + 3]);
                        }
                    }
                    #pragma unroll
                    for (int m = 0; m < 32; m++) {
                        float e = fmaxf(acc[m], 0.f);
                        const float* w3r = sm->w3t + (mb + m) * 16;
                        #pragma unroll
                        for (int t = 0; t < 16; t += 4) {
                            float4 w3v = *(const float4*)(w3r + t);
                            o16[t]     = fmaf(w3v.x, e, o16[t]);
                            o16[t + 1] = fmaf(w3v.y, e, o16[t + 1]);
                            o16[t + 2] = fmaf(w3v.z, e, o16[t + 2]);
                            o16[t + 3] = fmaf(w3v.w, e, o16[t + 3]);
                        }
                    }
                }
                // bias layout: [il][h][j], il-stride BROW, h-stride 18
                float* dst = sm->buf + ilM * BROW + jM;
                #pragma unroll
                for (int t = 0; t < 16; t++) dst[t * 18] = o16[t];
            }
        }
        __syncthreads();
        // ---- (c) qk + bias + softmax + conv1d weighting ----
        // Mapping: h = tid>>4, il = tid&15 -> ksh/qsh loads are warp-uniform broadcasts
        if (tid < 256) {
            const int h = tid >> 4, il = tid & 15;
            const int i = i0 + il;
            float* brow = sm->buf + il * BROW + h * 18;
            if (i < NSP) {
                float srow[18];
                #pragma unroll
                for (int j = 0; j < NJ; j++) srow[j] = brow[j];
                #pragma unroll
                for (int d = 0; d < DHEAD; d++) {
                    int c = h * 16 + d;
                    float qv = 0.25f * sm->qsh[(c * 56 + i) & 255];
                    const float4* kr4 = (const float4*)(sm->ksh + c * KROW);
                    float4 k0 = kr4[0], k1 = kr4[1], k2 = kr4[2], k3 = kr4[3];
                    float2 k4 = *(const float2*)(sm->ksh + c * KROW + 16);
                    srow[0]  = fmaf(qv, k0.x, srow[0]);  srow[1]  = fmaf(qv, k0.y, srow[1]);
                    srow[2]  = fmaf(qv, k0.z, srow[2]);  srow[3]  = fmaf(qv, k0.w, srow[3]);
                    srow[4]  = fmaf(qv, k1.x, srow[4]);  srow[5]  = fmaf(qv, k1.y, srow[5]);
                    srow[6]  = fmaf(qv, k1.z, srow[6]);  srow[7]  = fmaf(qv, k1.w, srow[7]);
                    srow[8]  = fmaf(qv, k2.x, srow[8]);  srow[9]  = fmaf(qv, k2.y, srow[9]);
                    srow[10] = fmaf(qv, k2.z, srow[10]); srow[11] = fmaf(qv, k2.w, srow[11]);
                    srow[12] = fmaf(qv, k3.x, srow[12]); srow[13] = fmaf(qv, k3.y, srow[13]);
                    srow[14] = fmaf(qv, k3.z, srow[14]); srow[15] = fmaf(qv, k3.w, srow[15]);
                    srow[16] = fmaf(qv, k4.x, srow[16]); srow[17] = fmaf(qv, k4.y, srow[17]);
                }
                float mx = srow[0];
                #pragma unroll
                for (int j = 1; j < NJ; j++) mx = fmaxf(mx, srow[j]);
                float ssum = 0.f;
                #pragma unroll
                for (int j = 0; j < NJ; j++) { float e = __expf(srow[j] - mx); srow[j] = e; ssum += e; }
                float sc = sm->cw[i] / ssum;
                #pragma unroll
                for (int j = 0; j < NJ; j++) brow[j] = srow[j] * sc;
            } else {
                #pragma unroll
                for (int j = 0; j < NJ; j++) brow[j] = 0.f;
            }
        }
        __syncthreads();
        // ---- (e) reduce over il into A: one (h,j) pair per thread, all 288 ----
        {
            const float* src = sm->buf + hA * 18 + jA;
            float a = 0.f;
            #pragma unroll
            for (int il = 0; il < TI; il++) a += src[il * BROW];
            A_reg += a;
        }
        __syncthreads();
    }
    sm->Ash[hA * NJ + jA] = A_reg;
    __syncthreads();

    // ================= Tail: pooled attention output -> w_out -> residual -> LN =================
    if (tid < 256) {
        const int h = tid >> 4;
        const float* vr = sm->vsh + tid * KROW;
        const float* Ar = sm->Ash + h * NJ;
        float acc = 0.f;
        #pragma unroll
        for (int j = 0; j < NJ; j++) acc = fmaf(Ar[j], vr[j], acc);
        sm->pp[tid] = acc;
    }
    __syncthreads();
    {
        float y = 0.f;
        if (tid < 256) {
            float s0 = 0.f, s1 = 0.f, s2 = 0.f, s3 = 0.f;
            for (int t = 0; t < NSP; t += 4) {
                s0 += sm->cw[t]; s1 += sm->cw[t + 1]; s2 += sm->cw[t + 2]; s3 += sm->cw[t + 3];
            }
            float sumcw = (s0 + s1) + (s2 + s3);
            float acc = sumcw * __ldg(b_out + tid) + __ldg(conv1d_b);
            const float* wor = w_out + tid * ND;
            for (int c = 0; c < ND; c += 4) {
                float4 w4 = *(const float4*)(wor + c);
                acc = fmaf(w4.x, sm->pp[c],     acc);
                acc = fmaf(w4.y, sm->pp[c + 1], acc);
                acc = fmaf(w4.z, sm->pp[c + 2], acc);
                acc = fmaf(w4.w, sm->pp[c + 3], acc);
            }
            y = acc + sm->qsh[tid];
            float s = y, sq = y * y;
            #pragma unroll
            for (int o = 16; o > 0; o >>= 1) {
                s  += __shfl_xor_sync(0xffffffffu, s,  o);
                sq += __shfl_xor_sync(0xffffffffu, sq, o);
            }
            if (lane == 0) { sm->red[wid] = s; sm->red[8 + wid] = sq; }
        }
        __syncthreads();
        if (tid == 0) {
            float t1 = 0.f, t2 = 0.f;
            #pragma unroll
            for (int w8 = 0; w8 < 8; w8++) { t1 += sm->red[w8]; t2 += sm->red[8 + w8]; }
            float mu = t1 * (1.0f / 256.0f);
            sm->stats[0] = mu;
            sm->stats[1] = t2 * (1.0f / 256.0f) - mu * mu;
        }
        __syncthreads();
        if (tid < 256) {
            float mu = sm->stats[0], var = sm->stats[1];
            out[b * ND + tid] = (y - mu) * rsqrtf(var + 1e-5f) * __ldg(ln_g + tid) + __ldg(ln_b + tid);
        }
    }
}

extern "C" void kernel_launch(void* const* d_in, const int* in_sizes, int n_in,
                              void* d_out, int out_size)
{
    const float* x        = (const float*)d_in[0];
    const float* q        = (const float*)d_in[1];
    const float* w_off_dw = (const float*)d_in[2];
    const float* b_off_dw = (const float*)d_in[3];
    const float* w_off_pw = (const float*)d_in[4];
    const float* wk       = (const float*)d_in[5];
    const float* wv       = (const float*)d_in[6];
    const float* w_out    = (const float*)d_in[7];
    const float* b_out    = (const float*)d_in[8];
    const float* cpb_w1   = (const float*)d_in[9];
    const float* cpb_b1   = (const float*)d_in[10];
    const float* cpb_w2   = (const float*)d_in[11];
    const float* cpb_b2   = (const float*)d_in[12];
    const float* cpb_w3   = (const float*)d_in[13];
    const float* cpb_b3   = (const float*)d_in[14];
    const float* conv1d_w = (const float*)d_in[15];
    const float* conv1d_b = (const float*)d_in[16];
    const float* ln_g     = (const float*)d_in[17];
    const float* ln_b     = (const float*)d_in[18];
    float* out = (float*)d_out;

    (void)in_sizes; (void)n_in; (void)out_size;

    cudaFuncSetAttribute(sca_kernel, cudaFuncAttributeMaxDynamicSharedMemorySize, (int)sizeof(SM));
    sca_kernel<<<NB, NTHR, sizeof(SM)>>>(x, q, w_off_dw, b_off_dw, w_off_pw, wk, wv,
                                         w_out, b_out, cpb_w1, cpb_b1, cpb_w2, cpb_b2,
                                         cpb_w3, cpb_b3, conv1d_w, conv1d_b, ln_g, ln_b, out);
}